// round 14
// baseline (speedup 1.0000x reference)
#include <cuda_runtime.h>
#include <cuda_bf16.h>
#include <math.h>

#define Bdim 256
#define Gdim 2048
#define Fdim 128
#define Rdim 512
#define Kdim 128

__device__ float g_scorer[Bdim * Fdim];
__device__ float g_norm[Bdim];
__device__ float g_scores[Bdim * Gdim];

__device__ __forceinline__ float tanh_fast(float x) {
    float y;
    asm("tanh.approx.f32 %0, %1;" : "=f"(y) : "f"(x));
    return y;
}
__device__ __forceinline__ unsigned f2sortable(float v) {
    unsigned u = __float_as_uint(v);
    return (u & 0x80000000u) ? ~u : (u | 0x80000000u);
}
__device__ __forceinline__ float sortable2f(unsigned u) {
    return __uint_as_float((u & 0x80000000u) ? (u ^ 0x80000000u) : ~u);
}
__device__ __forceinline__ unsigned long long umax64(unsigned long long a, unsigned long long b) { return a > b ? a : b; }
__device__ __forceinline__ unsigned long long umin64(unsigned long long a, unsigned long long b) { return a < b ? a : b; }

// ---------------------------------------------------------------------------
// Kernel 1: scorer = tanh(h_t @ W_map + b_map) and per-row norm.
// FROZEN FP ORDER (passed rounds 5-11 at rel_err 2.5e-6; R12 showed any
// reduction-order change can flip a top-k tie): 256 blocks x 512 threads,
// per-thread serial over 32 r's, 16-partial smem sum in fixed order.
// ---------------------------------------------------------------------------
__global__ void __launch_bounds__(512)
scorer_kernel(const float* __restrict__ h_t,
              const float* __restrict__ W,
              const float* __restrict__ bmap) {
    const int b = blockIdx.x;
    const int f4 = threadIdx.x & 31;
    const int rc = threadIdx.x >> 5;   // 0..15
    __shared__ float sh[Rdim];
    __shared__ float4 partial[16][32];
    __shared__ float red[4];

    if (threadIdx.x < Rdim) sh[threadIdx.x] = h_t[b * Rdim + threadIdx.x];
    __syncthreads();

    const float4* W4 = reinterpret_cast<const float4*>(W);
    float4 acc = make_float4(0.f, 0.f, 0.f, 0.f);
    const int rbase = rc * 32;
#pragma unroll
    for (int r = 0; r < 32; r++) {
        float h = sh[rbase + r];
        float4 w = W4[(size_t)(rbase + r) * 32 + f4];
        acc.x = fmaf(h, w.x, acc.x);
        acc.y = fmaf(h, w.y, acc.y);
        acc.z = fmaf(h, w.z, acc.z);
        acc.w = fmaf(h, w.w, acc.w);
    }
    partial[rc][f4] = acc;
    __syncthreads();

    if (threadIdx.x < Fdim) {
        const int f = threadIdx.x;
        const float* pc = reinterpret_cast<const float*>(partial);  // [16][128]
        float sum = bmap[f];
#pragma unroll
        for (int c = 0; c < 16; c++) sum += pc[c * 128 + f];
        float sc = tanhf(sum);   // precise: feeds ordering
        g_scorer[b * Fdim + f] = sc;
        float sq = sc * sc;
#pragma unroll
        for (int off = 16; off > 0; off >>= 1)
            sq += __shfl_xor_sync(0xFFFFFFFFu, sq, off);
        if ((f & 31) == 0) red[f >> 5] = sq;
    }
    __syncthreads();
    if (threadIdx.x == 0)
        g_norm[b] = sqrtf(red[0] + red[1] + red[2] + red[3]);
}

// ---------------------------------------------------------------------------
// Kernel 2: scores[b,g] = dot(node[b,g,:], scorer[b,:]) / norm + mask[b,g]
// Grid (16, 256) x 256 threads; warp: 16 rows, loads up-front, streaming.
// ---------------------------------------------------------------------------
__global__ void scores_kernel(const float* __restrict__ node,
                              const float* __restrict__ mask) {
    const int b = blockIdx.y;
    const int g0 = blockIdx.x * 128;
    __shared__ float s_sc[Fdim];
    __shared__ float s_inv;

    if (threadIdx.x < Fdim) s_sc[threadIdx.x] = g_scorer[b * Fdim + threadIdx.x];
    if (threadIdx.x == 0) s_inv = 1.0f / g_norm[b];
    __syncthreads();

    const int warp = threadIdx.x >> 5;
    const int lane = threadIdx.x & 31;
    const float4 sc = reinterpret_cast<const float4*>(s_sc)[lane];
    const float inv = s_inv;
    const float4* nrow = reinterpret_cast<const float4*>(node) + ((size_t)b * Gdim) * 32;
    const float4* mask4 = reinterpret_cast<const float4*>(mask + (size_t)b * Gdim);
    float4* out4 = reinterpret_cast<float4*>(g_scores + b * Gdim);

    const int r0 = g0 + warp * 16;
    float4 a[16];
    float d[16];
#pragma unroll
    for (int i = 0; i < 16; i++) a[i] = __ldcs(&nrow[(size_t)(r0 + i) * 32 + lane]);
#pragma unroll
    for (int i = 0; i < 16; i++)
        d[i] = a[i].x * sc.x + a[i].y * sc.y + a[i].z * sc.z + a[i].w * sc.w;
#pragma unroll
    for (int off = 16; off > 0; off >>= 1) {
#pragma unroll
        for (int i = 0; i < 16; i++) d[i] += __shfl_xor_sync(0xFFFFFFFFu, d[i], off);
    }
    if (lane == 0) {
#pragma unroll
        for (int q = 0; q < 4; q++) {
            float4 m = mask4[(r0 >> 2) + q];
            float4 o;
            o.x = d[q * 4 + 0] * inv + m.x;
            o.y = d[q * 4 + 1] * inv + m.y;
            o.z = d[q * 4 + 2] * inv + m.z;
            o.w = d[q * 4 + 3] * inv + m.w;
            __stcs(&out4[(r0 >> 2) + q], o);
        }
    }
}

// ---------------------------------------------------------------------------
// Kernel 3: merge-prune top-k + LSE + policy + gather/transpose.
// ---------------------------------------------------------------------------
__global__ void __launch_bounds__(512)
topk_gather_kernel(const float* __restrict__ node,
                   float* __restrict__ out,
                   float* __restrict__ out_policy) {
    const int b = blockIdx.x;
    const int t = threadIdx.x;
    const int warp = t >> 5;     // 0..15
    const int lane = t & 31;
    __shared__ union {
        unsigned long long keys[Gdim];  // 16 KB (sort)
        float tile[Kdim][33];           // 16.9 KB (gather)
    } u;
    __shared__ int   s_idx[Kdim];
    __shared__ float s_tv[Kdim];
    __shared__ float red_a[16];
    __shared__ float red_b[16];

    unsigned long long k[4];
#pragma unroll
    for (int i = 0; i < 4; i++) {
        int e = warp * 128 + 4 * lane + i;
        float v = __ldcs(&g_scores[b * Gdim + e]);
        k[i] = ((unsigned long long)f2sortable(v) << 32) |
               (unsigned)(0xFFFFFFFFu - (unsigned)e);
    }

#define CMP_PAIR(lo, hi, desc)                                   \
    { unsigned long long _a = k[lo], _b = k[hi];                  \
      k[lo] = (desc) ? umax64(_a, _b) : umin64(_a, _b);           \
      k[hi] = (desc) ? umin64(_a, _b) : umax64(_a, _b); }

    CMP_PAIR(0, 1, true)
    CMP_PAIR(2, 3, false)
#pragma unroll
    for (int kk = 4; kk <= 128; kk <<= 1) {
        const int kkq = kk >> 2;
        const bool descT = ((lane & kkq) == 0);
#pragma unroll
        for (int j = (kk >> 1) < 64 ? (kk >> 1) : 64; j >= 4; j >>= 1) {
            const int jq = j >> 2;
            const bool keepmax = (descT != ((lane & jq) != 0));
#pragma unroll
            for (int i = 0; i < 4; i++) {
                unsigned long long o = __shfl_xor_sync(0xFFFFFFFFu, k[i], jq);
                k[i] = keepmax ? umax64(k[i], o) : umin64(k[i], o);
            }
        }
        CMP_PAIR(0, 2, descT)
        CMP_PAIR(1, 3, descT)
        CMP_PAIR(0, 1, descT)
        CMP_PAIR(2, 3, descT)
    }

#pragma unroll
    for (int i = 0; i < 4; i++) u.keys[warp * 128 + 4 * lane + i] = k[i];
    if (lane == 0) red_a[warp] = sortable2f((unsigned)(k[0] >> 32));
    __syncthreads();

    float maxv = red_a[0];
#pragma unroll
    for (int w = 1; w < 16; w++) maxv = fmaxf(maxv, red_a[w]);

    {
        float su = 0.f;
#pragma unroll
        for (int i = 0; i < 4; i++)
            su += __expf(sortable2f((unsigned)(k[i] >> 32)) - maxv);
#pragma unroll
        for (int off = 16; off > 0; off >>= 1)
            su += __shfl_xor_sync(0xFFFFFFFFu, su, off);
        if (lane == 0) red_b[warp] = su;
    }
    __syncthreads();
    float lse;
    {
        float tot = 0.f;
#pragma unroll
        for (int w = 0; w < 16; w++) tot += red_b[w];
        lse = __logf(tot);
    }

#define MPAIR(lo, hi)                                            \
    { unsigned long long _a = m[lo], _b = m[hi];                  \
      m[lo] = umax64(_a, _b); m[hi] = umin64(_a, _b); }

#pragma unroll
    for (int npairs = 8; npairs >= 1; npairs >>= 1) {
        unsigned long long m[4];
        const bool active = (warp < npairs);
        if (active) {
            const int Abase = 2 * warp * 128;
            const int Bbase = Abase + 128;
#pragma unroll
            for (int i = 0; i < 4; i++) {
                const int el = 4 * lane + i;
                unsigned long long a = u.keys[Abase + el];
                unsigned long long bb = u.keys[Bbase + 127 - el];
                m[i] = umax64(a, bb);
            }
#pragma unroll
            for (int j = 64; j >= 4; j >>= 1) {
                const int jq = j >> 2;
                const bool keepmax = ((lane & jq) == 0);
#pragma unroll
                for (int i = 0; i < 4; i++) {
                    unsigned long long o = __shfl_xor_sync(0xFFFFFFFFu, m[i], jq);
                    m[i] = keepmax ? umax64(m[i], o) : umin64(m[i], o);
                }
            }
            MPAIR(0, 2) MPAIR(1, 3) MPAIR(0, 1) MPAIR(2, 3)
        }
        __syncthreads();
        if (active) {
#pragma unroll
            for (int i = 0; i < 4; i++) u.keys[warp * 128 + 4 * lane + i] = m[i];
        }
        __syncthreads();
    }
#undef MPAIR
#undef CMP_PAIR

    if (t < Kdim) {
        unsigned long long kk = u.keys[t];
        float v = sortable2f((unsigned)(kk >> 32));
        s_idx[t] = (int)(0xFFFFFFFFu - (unsigned)(kk & 0xFFFFFFFFu));
        s_tv[t]  = tanh_fast(v);
        float p = v - maxv - lse;
#pragma unroll
        for (int off = 16; off > 0; off >>= 1)
            p += __shfl_xor_sync(0xFFFFFFFFu, p, off);
        if (lane == 0) red_a[warp] = p;
    }
    __syncthreads();
    if (t == 0)
        out_policy[b] = (red_a[0] + red_a[1] + red_a[2] + red_a[3]) * (1.0f / Kdim);

    const int row = t >> 2;
    const int q   = t & 3;
    const int idx = s_idx[row];
    const float tv = s_tv[row];
    const float4* node4 = reinterpret_cast<const float4*>(node) +
                          ((size_t)b * Gdim + idx) * 32;
    float4 vv[8];
#pragma unroll
    for (int s4 = 0; s4 < 4; s4++)
#pragma unroll
        for (int ii = 0; ii < 2; ii++)
            vv[s4 * 2 + ii] = __ldcs(&node4[s4 * 8 + q * 2 + ii]);

    const int kq = t & 127;
    const int fq = t >> 7;  // 0..3
#pragma unroll
    for (int s4 = 0; s4 < 4; s4++) {
        __syncthreads();
#pragma unroll
        for (int ii = 0; ii < 2; ii++) {
            const float4 w = vv[s4 * 2 + ii];
            const int fl = (q * 2 + ii) * 4;
            u.tile[row][fl + 0] = w.x * tv;
            u.tile[row][fl + 1] = w.y * tv;
            u.tile[row][fl + 2] = w.z * tv;
            u.tile[row][fl + 3] = w.w * tv;
        }
        __syncthreads();
#pragma unroll
        for (int i = 0; i < 8; i++) {
            int fl = fq + i * 4;
            __stcs(&out[((size_t)b * Fdim + s4 * 32 + fl) * Kdim + kq], u.tile[kq][fl]);
        }
    }
}

// ---------------------------------------------------------------------------
extern "C" void kernel_launch(void* const* d_in, const int* in_sizes, int n_in,
                              void* d_out, int out_size) {
    const float* node  = (const float*)d_in[0];
    const float* mask  = (const float*)d_in[1];
    const float* h_t   = (const float*)d_in[2];
    const float* W_map = (const float*)d_in[3];
    const float* b_map = (const float*)d_in[4];

    float* out = (float*)d_out;
    float* out_policy = out + (size_t)Bdim * Fdim * Kdim;

    scorer_kernel<<<Bdim, 512>>>(h_t, W_map, b_map);
    {
        dim3 grid(Gdim / 128, Bdim);
        scores_kernel<<<grid, 256>>>(node, mask);
    }
    topk_gather_kernel<<<Bdim, 512>>>(node, out, out_policy);
}

// round 16
// speedup vs baseline: 1.0818x; 1.0818x over previous
#include <cuda_runtime.h>
#include <cuda_bf16.h>
#include <math.h>

#define Bdim 256
#define Gdim 2048
#define Fdim 128
#define Rdim 512
#define Kdim 128

__device__ float g_scorer[Bdim * Fdim];
__device__ float g_norm[Bdim];
__device__ float g_scores[Bdim * Gdim];

__device__ __forceinline__ float tanh_fast(float x) {
    float y;
    asm("tanh.approx.f32 %0, %1;" : "=f"(y) : "f"(x));
    return y;
}
__device__ __forceinline__ unsigned f2sortable(float v) {
    unsigned u = __float_as_uint(v);
    return (u & 0x80000000u) ? ~u : (u | 0x80000000u);
}
__device__ __forceinline__ float sortable2f(unsigned u) {
    return __uint_as_float((u & 0x80000000u) ? (u ^ 0x80000000u) : ~u);
}
__device__ __forceinline__ unsigned long long umax64(unsigned long long a, unsigned long long b) { return a > b ? a : b; }
__device__ __forceinline__ unsigned long long umin64(unsigned long long a, unsigned long long b) { return a < b ? a : b; }

// ---------------------------------------------------------------------------
// Kernel 1: scorer = tanh(h_t @ W_map + b_map) and per-row norm.
// FROZEN FP ORDER (R12 showed reduction-order changes flip top-k ties).
// Fires PDL trigger early so scores_kernel CTAs can launch underneath.
// ---------------------------------------------------------------------------
__global__ void __launch_bounds__(512)
scorer_kernel(const float* __restrict__ h_t,
              const float* __restrict__ W,
              const float* __restrict__ bmap) {
    cudaTriggerProgrammaticLaunchCompletion();  // launch-gate only; data gated by griddepsync
    const int b = blockIdx.x;
    const int f4 = threadIdx.x & 31;
    const int rc = threadIdx.x >> 5;   // 0..15
    __shared__ float sh[Rdim];
    __shared__ float4 partial[16][32];
    __shared__ float red[4];

    if (threadIdx.x < Rdim) sh[threadIdx.x] = h_t[b * Rdim + threadIdx.x];
    __syncthreads();

    const float4* W4 = reinterpret_cast<const float4*>(W);
    float4 acc = make_float4(0.f, 0.f, 0.f, 0.f);
    const int rbase = rc * 32;
#pragma unroll
    for (int r = 0; r < 32; r++) {
        float h = sh[rbase + r];
        float4 w = W4[(size_t)(rbase + r) * 32 + f4];
        acc.x = fmaf(h, w.x, acc.x);
        acc.y = fmaf(h, w.y, acc.y);
        acc.z = fmaf(h, w.z, acc.z);
        acc.w = fmaf(h, w.w, acc.w);
    }
    partial[rc][f4] = acc;
    __syncthreads();

    if (threadIdx.x < Fdim) {
        const int f = threadIdx.x;
        const float* pc = reinterpret_cast<const float*>(partial);  // [16][128]
        float sum = bmap[f];
#pragma unroll
        for (int c = 0; c < 16; c++) sum += pc[c * 128 + f];
        float sc = tanhf(sum);   // precise: feeds ordering
        g_scorer[b * Fdim + f] = sc;
        float sq = sc * sc;
#pragma unroll
        for (int off = 16; off > 0; off >>= 1)
            sq += __shfl_xor_sync(0xFFFFFFFFu, sq, off);
        if ((f & 31) == 0) red[f >> 5] = sq;
    }
    __syncthreads();
    if (threadIdx.x == 0)
        g_norm[b] = sqrtf(red[0] + red[1] + red[2] + red[3]);
}

// ---------------------------------------------------------------------------
// Kernel 2: scores[b,g] = dot(node[b,g,:], scorer[b,:]) / norm + mask[b,g]
// PDL: node loads issued BEFORE griddepsync (addresses independent of
// scorer) -> HBM stream overlaps scorer's tail.
// ---------------------------------------------------------------------------
__global__ void scores_kernel(const float* __restrict__ node,
                              const float* __restrict__ mask) {
    const int b = blockIdx.y;
    const int g0 = blockIdx.x * 128;
    __shared__ float s_sc[Fdim];
    __shared__ float s_inv;

    const int warp = threadIdx.x >> 5;
    const int lane = threadIdx.x & 31;
    const float4* nrow = reinterpret_cast<const float4*>(node) + ((size_t)b * Gdim) * 32;
    const int r0 = g0 + warp * 16;

    // issue the big loads first (independent of scorer output)
    float4 a[16];
#pragma unroll
    for (int i = 0; i < 16; i++) a[i] = __ldcs(&nrow[(size_t)(r0 + i) * 32 + lane]);

    cudaGridDependencySynchronize();   // scorer writes now visible

    if (threadIdx.x < Fdim) s_sc[threadIdx.x] = g_scorer[b * Fdim + threadIdx.x];
    if (threadIdx.x == 0) s_inv = 1.0f / g_norm[b];
    __syncthreads();

    const float4 sc = reinterpret_cast<const float4*>(s_sc)[lane];
    const float inv = s_inv;
    const float4* mask4 = reinterpret_cast<const float4*>(mask + (size_t)b * Gdim);
    float4* out4 = reinterpret_cast<float4*>(g_scores + b * Gdim);

    float d[16];
#pragma unroll
    for (int i = 0; i < 16; i++)
        d[i] = a[i].x * sc.x + a[i].y * sc.y + a[i].z * sc.z + a[i].w * sc.w;
#pragma unroll
    for (int off = 16; off > 0; off >>= 1) {
#pragma unroll
        for (int i = 0; i < 16; i++) d[i] += __shfl_xor_sync(0xFFFFFFFFu, d[i], off);
    }
    if (lane == 0) {
#pragma unroll
        for (int q = 0; q < 4; q++) {
            float4 m = mask4[(r0 >> 2) + q];
            float4 o;
            o.x = d[q * 4 + 0] * inv + m.x;
            o.y = d[q * 4 + 1] * inv + m.y;
            o.z = d[q * 4 + 2] * inv + m.z;
            o.w = d[q * 4 + 3] * inv + m.w;
            __stcs(&out4[(r0 >> 2) + q], o);
        }
    }
}

// ---------------------------------------------------------------------------
// Kernel 3: merge-prune top-k + LSE + policy + gather/transpose.
// PDL: launches under scores' tail; griddepsync before reading g_scores.
// ---------------------------------------------------------------------------
__global__ void __launch_bounds__(512)
topk_gather_kernel(const float* __restrict__ node,
                   float* __restrict__ out,
                   float* __restrict__ out_policy) {
    const int b = blockIdx.x;
    const int t = threadIdx.x;
    const int warp = t >> 5;     // 0..15
    const int lane = t & 31;
    __shared__ union {
        unsigned long long keys[Gdim];  // 16 KB (sort)
        float tile[Kdim][33];           // 16.9 KB (gather)
    } u;
    __shared__ int   s_idx[Kdim];
    __shared__ float s_tv[Kdim];
    __shared__ float red_a[16];
    __shared__ float red_b[16];

    cudaGridDependencySynchronize();   // g_scores now complete

    unsigned long long k[4];
#pragma unroll
    for (int i = 0; i < 4; i++) {
        int e = warp * 128 + 4 * lane + i;
        float v = __ldcs(&g_scores[b * Gdim + e]);
        k[i] = ((unsigned long long)f2sortable(v) << 32) |
               (unsigned)(0xFFFFFFFFu - (unsigned)e);
    }

#define CMP_PAIR(lo, hi, desc)                                   \
    { unsigned long long _a = k[lo], _b = k[hi];                  \
      k[lo] = (desc) ? umax64(_a, _b) : umin64(_a, _b);           \
      k[hi] = (desc) ? umin64(_a, _b) : umax64(_a, _b); }

    CMP_PAIR(0, 1, true)
    CMP_PAIR(2, 3, false)
#pragma unroll
    for (int kk = 4; kk <= 128; kk <<= 1) {
        const int kkq = kk >> 2;
        const bool descT = ((lane & kkq) == 0);
#pragma unroll
        for (int j = (kk >> 1) < 64 ? (kk >> 1) : 64; j >= 4; j >>= 1) {
            const int jq = j >> 2;
            const bool keepmax = (descT != ((lane & jq) != 0));
#pragma unroll
            for (int i = 0; i < 4; i++) {
                unsigned long long o = __shfl_xor_sync(0xFFFFFFFFu, k[i], jq);
                k[i] = keepmax ? umax64(k[i], o) : umin64(k[i], o);
            }
        }
        CMP_PAIR(0, 2, descT)
        CMP_PAIR(1, 3, descT)
        CMP_PAIR(0, 1, descT)
        CMP_PAIR(2, 3, descT)
    }

#pragma unroll
    for (int i = 0; i < 4; i++) u.keys[warp * 128 + 4 * lane + i] = k[i];
    if (lane == 0) red_a[warp] = sortable2f((unsigned)(k[0] >> 32));
    __syncthreads();

    float maxv = red_a[0];
#pragma unroll
    for (int w = 1; w < 16; w++) maxv = fmaxf(maxv, red_a[w]);

    {
        float su = 0.f;
#pragma unroll
        for (int i = 0; i < 4; i++)
            su += __expf(sortable2f((unsigned)(k[i] >> 32)) - maxv);
#pragma unroll
        for (int off = 16; off > 0; off >>= 1)
            su += __shfl_xor_sync(0xFFFFFFFFu, su, off);
        if (lane == 0) red_b[warp] = su;
    }
    __syncthreads();
    float lse;
    {
        float tot = 0.f;
#pragma unroll
        for (int w = 0; w < 16; w++) tot += red_b[w];
        lse = __logf(tot);
    }

#define MPAIR(lo, hi)                                            \
    { unsigned long long _a = m[lo], _b = m[hi];                  \
      m[lo] = umax64(_a, _b); m[hi] = umin64(_a, _b); }

#pragma unroll
    for (int npairs = 8; npairs >= 1; npairs >>= 1) {
        unsigned long long m[4];
        const bool active = (warp < npairs);
        if (active) {
            const int Abase = 2 * warp * 128;
            const int Bbase = Abase + 128;
#pragma unroll
            for (int i = 0; i < 4; i++) {
                const int el = 4 * lane + i;
                unsigned long long a = u.keys[Abase + el];
                unsigned long long bb = u.keys[Bbase + 127 - el];
                m[i] = umax64(a, bb);
            }
#pragma unroll
            for (int j = 64; j >= 4; j >>= 1) {
                const int jq = j >> 2;
                const bool keepmax = ((lane & jq) == 0);
#pragma unroll
                for (int i = 0; i < 4; i++) {
                    unsigned long long o = __shfl_xor_sync(0xFFFFFFFFu, m[i], jq);
                    m[i] = keepmax ? umax64(m[i], o) : umin64(m[i], o);
                }
            }
            MPAIR(0, 2) MPAIR(1, 3) MPAIR(0, 1) MPAIR(2, 3)
        }
        __syncthreads();
        if (active) {
#pragma unroll
            for (int i = 0; i < 4; i++) u.keys[warp * 128 + 4 * lane + i] = m[i];
        }
        __syncthreads();
    }
#undef MPAIR
#undef CMP_PAIR

    if (t < Kdim) {
        unsigned long long kk = u.keys[t];
        float v = sortable2f((unsigned)(kk >> 32));
        s_idx[t] = (int)(0xFFFFFFFFu - (unsigned)(kk & 0xFFFFFFFFu));
        s_tv[t]  = tanh_fast(v);
        float p = v - maxv - lse;
#pragma unroll
        for (int off = 16; off > 0; off >>= 1)
            p += __shfl_xor_sync(0xFFFFFFFFu, p, off);
        if (lane == 0) red_a[warp] = p;
    }
    __syncthreads();
    if (t == 0)
        out_policy[b] = (red_a[0] + red_a[1] + red_a[2] + red_a[3]) * (1.0f / Kdim);

    const int row = t >> 2;
    const int q   = t & 3;
    const int idx = s_idx[row];
    const float tv = s_tv[row];
    const float4* node4 = reinterpret_cast<const float4*>(node) +
                          ((size_t)b * Gdim + idx) * 32;
    float4 vv[8];
#pragma unroll
    for (int s4 = 0; s4 < 4; s4++)
#pragma unroll
        for (int ii = 0; ii < 2; ii++)
            vv[s4 * 2 + ii] = __ldcs(&node4[s4 * 8 + q * 2 + ii]);

    const int kq = t & 127;
    const int fq = t >> 7;  // 0..3
#pragma unroll
    for (int s4 = 0; s4 < 4; s4++) {
        __syncthreads();
#pragma unroll
        for (int ii = 0; ii < 2; ii++) {
            const float4 w = vv[s4 * 2 + ii];
            const int fl = (q * 2 + ii) * 4;
            u.tile[row][fl + 0] = w.x * tv;
            u.tile[row][fl + 1] = w.y * tv;
            u.tile[row][fl + 2] = w.z * tv;
            u.tile[row][fl + 3] = w.w * tv;
        }
        __syncthreads();
#pragma unroll
        for (int i = 0; i < 8; i++) {
            int fl = fq + i * 4;
            __stcs(&out[((size_t)b * Fdim + s4 * 32 + fl) * Kdim + kq], u.tile[kq][fl]);
        }
    }
}

// ---------------------------------------------------------------------------
extern "C" void kernel_launch(void* const* d_in, const int* in_sizes, int n_in,
                              void* d_out, int out_size) {
    const float* node  = (const float*)d_in[0];
    const float* mask  = (const float*)d_in[1];
    const float* h_t   = (const float*)d_in[2];
    const float* W_map = (const float*)d_in[3];
    const float* b_map = (const float*)d_in[4];

    float* out = (float*)d_out;
    float* out_policy = out + (size_t)Bdim * Fdim * Kdim;

    scorer_kernel<<<Bdim, 512>>>(h_t, W_map, b_map);

    // scores with PDL: launches under scorer's tail
    {
        cudaLaunchConfig_t cfg = {};
        cfg.gridDim = dim3(Gdim / 128, Bdim, 1);
        cfg.blockDim = dim3(256, 1, 1);
        cudaLaunchAttribute attr[1];
        attr[0].id = cudaLaunchAttributeProgrammaticStreamSerialization;
        attr[0].val.programmaticStreamSerializationAllowed = 1;
        cfg.attrs = attr;
        cfg.numAttrs = 1;
        cudaLaunchKernelEx(&cfg, scores_kernel, node, mask);
    }

    // topk with PDL: launch ramp hidden under scores' tail
    {
        cudaLaunchConfig_t cfg = {};
        cfg.gridDim = dim3(Bdim, 1, 1);
        cfg.blockDim = dim3(512, 1, 1);
        cudaLaunchAttribute attr[1];
        attr[0].id = cudaLaunchAttributeProgrammaticStreamSerialization;
        attr[0].val.programmaticStreamSerializationAllowed = 1;
        cfg.attrs = attr;
        cfg.numAttrs = 1;
        cudaLaunchKernelEx(&cfg, topk_gather_kernel, node, out, out_policy);
    }
}